// round 16
// baseline (speedup 1.0000x reference)
#include <cuda_runtime.h>
#include <cuda_fp16.h>
#include <cstdint>

#define BB 4
#define CC 64
#define NNPOS 4096
#define HH 64
#define WW 64

// Scratch (__device__ globals; no allocs allowed)
__device__ __half g_q[BB * NNPOS * CC];            // Q fp16 (B,N,C), x (0.125*log2e) folded
__device__ __half g_k[BB * CC * NNPOS];            // K fp16 (B,C,N)
__device__ __half g_v[BB * CC * NNPOS];            // V fp16 (B,C,N)
__device__ __half g_po[2 * BB * NNPOS * CC];       // per-half NORMALIZED partial O (B,N,C) fp16
__device__ float  g_pl[2 * BB * NNPOS];            // partial l per key-half

#define QSCALE 0.18033688011112293f   // 0.125 * log2(e)
#define ONES2 0x3C003C00u              // half2(1.0, 1.0)

// ---------------- helpers ----------------
__device__ __forceinline__ uint32_t h2u(__half2 h) { return *reinterpret_cast<uint32_t*>(&h); }
__device__ __forceinline__ uint32_t packh2(float a, float b) { return h2u(__floats2half2_rn(a, b)); }

__device__ __forceinline__ void ldsm4(uint32_t* r, uint32_t addr) {
    asm volatile("ldmatrix.sync.aligned.m8n8.x4.shared.b16 {%0,%1,%2,%3}, [%4];"
                 : "=r"(r[0]), "=r"(r[1]), "=r"(r[2]), "=r"(r[3]) : "r"(addr));
}
__device__ __forceinline__ void ldsm4t(uint32_t* r, uint32_t addr) {
    asm volatile("ldmatrix.sync.aligned.m8n8.x4.trans.shared.b16 {%0,%1,%2,%3}, [%4];"
                 : "=r"(r[0]), "=r"(r[1]), "=r"(r[2]), "=r"(r[3]) : "r"(addr));
}
__device__ __forceinline__ void mma16816(float* d, const uint32_t* a, uint32_t b0, uint32_t b1) {
    asm volatile("mma.sync.aligned.m16n8k16.row.col.f32.f16.f16.f32 "
                 "{%0,%1,%2,%3},{%4,%5,%6,%7},{%8,%9},{%0,%1,%2,%3};"
                 : "+f"(d[0]), "+f"(d[1]), "+f"(d[2]), "+f"(d[3])
                 : "r"(a[0]), "r"(a[1]), "r"(a[2]), "r"(a[3]), "r"(b0), "r"(b1));
}
__device__ __forceinline__ void mma16816h(uint32_t* d, const uint32_t* a, uint32_t b0, uint32_t b1) {
    asm volatile("mma.sync.aligned.m16n8k16.row.col.f16.f16.f16.f16 "
                 "{%0,%1},{%2,%3,%4,%5},{%6,%7},{%0,%1};"
                 : "+r"(d[0]), "+r"(d[1])
                 : "r"(a[0]), "r"(a[1]), "r"(a[2]), "r"(a[3]), "r"(b0), "r"(b1));
}
__device__ __forceinline__ void cpasync16(uint32_t dst, const void* src) {
    asm volatile("cp.async.cg.shared.global [%0], [%1], 16;" :: "r"(dst), "l"(src));
}
__device__ __forceinline__ void cpcommit() { asm volatile("cp.async.commit_group;"); }
__device__ __forceinline__ void cpwait0()  { asm volatile("cp.async.wait_group 0;"); }

__device__ __forceinline__ uint32_t ex2h2(uint32_t s) {
    uint32_t r;
    asm("ex2.approx.f16x2 %0, %1;" : "=r"(r) : "r"(s));
    return r;
}

// ---------------------------------------------------------------------------
// 1) Fused prep: LN + qproj (HMMA) + dwconv(k,v). grid (32, B), 256 threads.
// ---------------------------------------------------------------------------
#define PR_XSTR  264
#define WQROWB   144
#define PR_WQ    0
#define PR_WK    9216
#define PR_WV    11520
#define PR_BQ    13824
#define PR_BK    14080
#define PR_BV    14336
#define PR_XS    14592
#define PREP_SMEM (PR_XS + 64 * PR_XSTR * 2)   // 48384

__global__ __launch_bounds__(256) void prep_kernel(
    const float* __restrict__ x,
    const float* __restrict__ ln_g, const float* __restrict__ ln_b,
    const float* __restrict__ wq, const float* __restrict__ bq,
    const float* __restrict__ wk, const float* __restrict__ bk,
    const float* __restrict__ wv, const float* __restrict__ bv)
{
    extern __shared__ char psm[];
    float* Wk  = (float*)(psm + PR_WK);
    float* Wv  = (float*)(psm + PR_WV);
    float* Bq  = (float*)(psm + PR_BQ);
    float* Bk  = (float*)(psm + PR_BK);
    float* Bv  = (float*)(psm + PR_BV);
    __half* Xs = (__half*)(psm + PR_XS);

    int tid = threadIdx.x;
    int h0 = blockIdx.x * 2;
    int b = blockIdx.y;

    // stage wq -> smem fp16 [o][c], stride WQROWB
    {
        int o = tid >> 2, qq = tid & 3;
        const float* src = wq + o * 64 + qq * 16;
        uint32_t hx[8];
#pragma unroll
        for (int u = 0; u < 8; u++) {
            float2 f2 = *(const float2*)(src + u * 2);
            hx[u] = packh2(f2.x, f2.y);
        }
        char* dst = psm + PR_WQ + o * WQROWB + qq * 32;
        *(uint4*)dst = make_uint4(hx[0], hx[1], hx[2], hx[3]);
        *(uint4*)(dst + 16) = make_uint4(hx[4], hx[5], hx[6], hx[7]);
    }
    for (int t = tid; t < 576; t += 256) { Wk[t] = wk[t]; Wv[t] = wv[t]; }
    if (tid < 64) { Bq[tid] = bq[tid]; Bk[tid] = bk[tid]; Bv[tid] = bv[tid]; }

    // Phase 1: LN rows h0-1 .. h0+2 (zero pad) -> Xs[c][tid]
    {
        int hh = tid >> 6;
        int w  = tid & 63;
        int h = h0 - 1 + hh;
        if (h >= 0 && h < HH) {
            const float* xp = x + (size_t)b * CC * NNPOS + h * WW + w;
            float vals[CC];
            float s = 0.f;
#pragma unroll
            for (int c = 0; c < CC; c++) { vals[c] = xp[(size_t)c * NNPOS]; s += vals[c]; }
            float mu = s * (1.f / 64.f);
            float vs = 0.f;
#pragma unroll
            for (int c = 0; c < CC; c++) { float d = vals[c] - mu; vs += d * d; }
            float rstd = rsqrtf(vs * (1.f / 64.f) + 1e-5f);
#pragma unroll
            for (int c = 0; c < CC; c++)
                Xs[c * PR_XSTR + tid] = __float2half_rn((vals[c] - mu) * rstd * __ldg(&ln_g[c]) + __ldg(&ln_b[c]));
        } else {
#pragma unroll
            for (int c = 0; c < CC; c++) Xs[c * PR_XSTR + tid] = __ushort_as_half((unsigned short)0);
        }
    }
    __syncthreads();

    // Phase 2: qproj via HMMA. warp w -> 16 positions.
    {
        int w = tid >> 5, lane = tid & 31;
        int g = lane >> 2, t4 = lane & 3;
        uint32_t xsbase = (uint32_t)__cvta_generic_to_shared(psm + PR_XS);
        uint32_t wqbase = (uint32_t)__cvta_generic_to_shared(psm + PR_WQ);

        int cA = (lane & 7) + ((lane & 16) >> 1);
        int posCh = ((lane >> 3) & 1) * 8;
        uint32_t aaddr = xsbase + (uint32_t)((cA * PR_XSTR + 64 + w * 16 + posCh) * 2);
        uint32_t qAf[4][4];
#pragma unroll
        for (int ks = 0; ks < 4; ks++)
            ldsm4t(qAf[ks], aaddr + (uint32_t)(ks * 16 * PR_XSTR * 2));

        int laneRowB = (lane & 7) + ((lane & 16) >> 1);
        int laneKB   = (lane & 8) << 1;
        uint32_t wqb = wqbase + (uint32_t)(laneRowB * WQROWB + laneKB);

        float dacc[8][4] = {};
#pragma unroll
        for (int it = 0; it < 16; it++) {
            int ks = it >> 2, np = it & 3;
            uint32_t b4[4];
            ldsm4(b4, wqb + (uint32_t)(np * (16 * WQROWB) + ks * 32));
            mma16816(dacc[2 * np],     qAf[ks], b4[0], b4[1]);
            mma16816(dacc[2 * np + 1], qAf[ks], b4[2], b4[3]);
        }

        int p0 = h0 * WW + w * 16 + g;
        __half* qr0 = g_q + (size_t)(b * NNPOS + p0) * CC;
        __half* qr8 = qr0 + 8 * CC;
#pragma unroll
        for (int nt = 0; nt < 8; nt++) {
            int o = nt * 8 + 2 * t4;
            float b0v = Bq[o], b1v = Bq[o + 1];
            *(uint32_t*)(qr0 + o) = packh2((dacc[nt][0] + b0v) * QSCALE,
                                           (dacc[nt][1] + b1v) * QSCALE);
            *(uint32_t*)(qr8 + o) = packh2((dacc[nt][2] + b0v) * QSCALE,
                                           (dacc[nt][3] + b1v) * QSCALE);
        }
    }

    // Phase 3: dwconv.
    {
        int c = tid >> 2, row = (tid >> 1) & 1, wh = tid & 1;
        int wst = wh * 32;
        float wkr[9], wvr[9];
#pragma unroll
        for (int i = 0; i < 9; i++) { wkr[i] = Wk[c * 9 + i]; wvr[i] = Wv[c * 9 + i]; }
        float bk0 = Bk[c], bv0 = Bv[c];
        uint32_t kh[16], vh[16];
#pragma unroll
        for (int ch = 0; ch < 4; ch++) {
            int w0 = wst + ch * 8;
            float ff[3][10];
#pragma unroll
            for (int r = 0; r < 3; r++) {
                const __half* src = Xs + c * PR_XSTR + (row + r) * 64 + (w0 - 2);
                float2 t0 = __half22float2(*(const __half2*)(src));
                float2 t1 = __half22float2(*(const __half2*)(src + 2));
                float2 t2 = __half22float2(*(const __half2*)(src + 4));
                float2 t3 = __half22float2(*(const __half2*)(src + 6));
                float2 t4v = __half22float2(*(const __half2*)(src + 8));
                float2 t5 = __half22float2(*(const __half2*)(src + 10));
                ff[r][0] = t0.y; ff[r][1] = t1.x; ff[r][2] = t1.y; ff[r][3] = t2.x; ff[r][4] = t2.y;
                ff[r][5] = t3.x; ff[r][6] = t3.y; ff[r][7] = t4v.x; ff[r][8] = t4v.y; ff[r][9] = t5.x;
            }
            if (w0 == 0)  { ff[0][0] = 0.f; ff[1][0] = 0.f; ff[2][0] = 0.f; }
            if (w0 == 56) { ff[0][9] = 0.f; ff[1][9] = 0.f; ff[2][9] = 0.f; }
            float ko[8], vo[8];
#pragma unroll
            for (int o = 0; o < 8; o++) {
                float sk = bk0, sv = bv0;
#pragma unroll
                for (int r = 0; r < 3; r++)
#pragma unroll
                    for (int d = 0; d < 3; d++) {
                        float xv = ff[r][o + d];
                        sk += xv * wkr[r * 3 + d];
                        sv += xv * wvr[r * 3 + d];
                    }
                ko[o] = sk; vo[o] = sv;
            }
#pragma unroll
            for (int j = 0; j < 4; j++) {
                kh[ch * 4 + j] = packh2(ko[2 * j], ko[2 * j + 1]);
                vh[ch * 4 + j] = packh2(vo[2 * j], vo[2 * j + 1]);
            }
        }
        size_t base = (size_t)(b * CC + c) * NNPOS + (h0 + row) * WW + wst;
        __half* kd = g_k + base;
        __half* vd = g_v + base;
        *(uint4*)(kd)      = make_uint4(kh[0],  kh[1],  kh[2],  kh[3]);
        *(uint4*)(kd + 8)  = make_uint4(kh[4],  kh[5],  kh[6],  kh[7]);
        *(uint4*)(kd + 16) = make_uint4(kh[8],  kh[9],  kh[10], kh[11]);
        *(uint4*)(kd + 24) = make_uint4(kh[12], kh[13], kh[14], kh[15]);
        *(uint4*)(vd)      = make_uint4(vh[0],  vh[1],  vh[2],  vh[3]);
        *(uint4*)(vd + 8)  = make_uint4(vh[4],  vh[5],  vh[6],  vh[7]);
        *(uint4*)(vd + 16) = make_uint4(vh[8],  vh[9],  vh[10], vh[11]);
        *(uint4*)(vd + 24) = make_uint4(vh[12], vh[13], vh[14], vh[15]);
    }
}

// ---------------------------------------------------------------------------
// 2) HMMA flash attention, split-KV. Partials: normalized O (fp16) + l (fp32).
//    grid (32, B, 2), 256 threads, 2 CTAs/SM.
// ---------------------------------------------------------------------------
#define TROWB 272
#define TBYTES (64 * TROWB)         // 17408
#define BUFB (2 * TBYTES)           // 34816
#define ATTN_SMEM (2 * BUFB)        // 69632

__device__ __forceinline__ void prefetch_tile(char* smp, int s, int b, int jt, int tid) {
    int c = tid >> 2, q = tid & 3;
    size_t src_off = (size_t)(b * CC + c) * NNPOS + jt + q * 32;
    uint32_t dst = (uint32_t)__cvta_generic_to_shared(smp + s * BUFB + c * TROWB + q * 64);
    const __half* ks = g_k + src_off;
    const __half* vs = g_v + src_off;
#pragma unroll
    for (int u = 0; u < 4; u++) cpasync16(dst + u * 16, ks + u * 8);
#pragma unroll
    for (int u = 0; u < 4; u++) cpasync16(dst + TBYTES + u * 16, vs + u * 8);
}

__global__ __launch_bounds__(256, 2) void attn_kernel() {
    extern __shared__ char smp[];
    int tid = threadIdx.x;
    int w = tid >> 5, lane = tid & 31;
    int b = blockIdx.y;
    int i0 = blockIdx.x * 128;
    int half = blockIdx.z;
    int jt0 = half * 2048;
    int g = lane >> 2, t4 = lane & 3;

    uint32_t loffK = (uint32_t)((lane & 15) * TROWB + ((lane >> 4) << 4));
    int laneRowB = (lane & 7) + ((lane & 16) >> 1);
    int laneKB   = (lane & 8) << 1;
    uint32_t loffV = (uint32_t)(laneRowB * TROWB + laneKB);
    uint32_t smbase = (uint32_t)__cvta_generic_to_shared(smp);

    prefetch_tile(smp, 0, b, jt0, tid);
    cpcommit();

    uint32_t qA[4][4];
    {
        size_t row0 = (size_t)(b * NNPOS + i0 + w * 16 + g) * CC;
        size_t row8 = row0 + 8 * CC;
#pragma unroll
        for (int ks = 0; ks < 4; ks++) {
            int col = 2 * t4 + 16 * ks;
            qA[ks][0] = *(const uint32_t*)(g_q + row0 + col);
            qA[ks][1] = *(const uint32_t*)(g_q + row8 + col);
            qA[ks][2] = *(const uint32_t*)(g_q + row0 + col + 8);
            qA[ks][3] = *(const uint32_t*)(g_q + row8 + col + 8);
        }
    }

    float oacc[8][4] = {};
    float lacc[4] = {};

    for (int tix = 0; tix < 16; tix++) {
        cpwait0();
        __syncthreads();
        if (tix < 15) { prefetch_tile(smp, (tix + 1) & 1, b, jt0 + (tix + 1) * 128, tid); cpcommit(); }

        uint32_t kb = smbase + (uint32_t)((tix & 1) * BUFB) + loffK;
        uint32_t vb = smbase + (uint32_t)((tix & 1) * BUFB + TBYTES) + loffV;

        // S = Q K^T (fp16 accumulate), K via trans-ldmatrix
        uint32_t sacc16[16][2];
#pragma unroll
        for (int i = 0; i < 16; i++) { sacc16[i][0] = 0u; sacc16[i][1] = 0u; }
        {
            uint32_t b4[2][4];
            ldsm4t(b4[0], kb);
#pragma unroll
            for (int it = 0; it < 32; it++) {
                int ks = it >> 3, np = it & 7;
                int cur = it & 1;
                if (it < 31) {
                    int nx = it + 1;
                    ldsm4t(b4[cur ^ 1], kb + (uint32_t)((nx & 7) * 32 + (nx >> 3) * (16 * TROWB)));
                }
                mma16816h(sacc16[2 * np],     qA[ks], b4[cur][0], b4[cur][1]);
                mma16816h(sacc16[2 * np + 1], qA[ks], b4[cur][2], b4[cur][3]);
            }
        }

        // p = 2^S; l via ones-MMA; O += P V^T
        {
            uint32_t v4[2][4];
            ldsm4(v4[0], vb);
#pragma unroll
            for (int ks2 = 0; ks2 < 8; ks2++) {
                uint32_t pA[4];
                pA[0] = ex2h2(sacc16[2 * ks2][0]);
                pA[1] = ex2h2(sacc16[2 * ks2][1]);
                pA[2] = ex2h2(sacc16[2 * ks2 + 1][0]);
                pA[3] = ex2h2(sacc16[2 * ks2 + 1][1]);
                mma16816(lacc, pA, ONES2, ONES2);
#pragma unroll
                for (int np = 0; np < 4; np++) {
                    int it = ks2 * 4 + np;
                    int cur = it & 1;
                    if (it < 31) {
                        int nx = it + 1;
                        ldsm4(v4[cur ^ 1], vb + (uint32_t)((nx & 3) * (16 * TROWB) + (nx >> 2) * 32));
                    }
                    mma16816(oacc[2 * np],     pA, v4[cur][0], v4[cur][1]);
                    mma16816(oacc[2 * np + 1], pA, v4[cur][2], v4[cur][3]);
                }
            }
        }
    }

    // write per-half NORMALIZED partial O (fp16) + partial l (fp32)
    int irow0 = i0 + w * 16 + g;
    float inv0 = 1.f / lacc[0], inv1 = 1.f / lacc[2];
    __half* po0 = g_po + (size_t)half * (BB * NNPOS * CC) + (size_t)(b * NNPOS + irow0) * CC;
    __half* po8 = po0 + 8 * CC;
#pragma unroll
    for (int nt = 0; nt < 8; nt++) {
        int c = nt * 8 + 2 * t4;
        *(uint32_t*)(po0 + c) = packh2(oacc[nt][0] * inv0, oacc[nt][1] * inv0);
        *(uint32_t*)(po8 + c) = packh2(oacc[nt][2] * inv1, oacc[nt][3] * inv1);
    }
    if (t4 == 0) {
        g_pl[half * (BB * NNPOS) + b * NNPOS + irow0]     = lacc[0];
        g_pl[half * (BB * NNPOS) + b * NNPOS + irow0 + 8] = lacc[2];
    }
}

// ---------------------------------------------------------------------------
// 3) Combine: O = w1*O1 + w2*O2 (w_i = l_i/(l1+l2)); out = O @ wo^T + bo + x.
// ---------------------------------------------------------------------------
#define WOROWB 144
#define COMB_SMEM (64 * WOROWB)

__global__ __launch_bounds__(256) void combine_kernel(const float* __restrict__ wo,
                                                      const float* __restrict__ bo,
                                                      const float* __restrict__ x,
                                                      float* __restrict__ out) {
    extern __shared__ char csm[];
    int tid = threadIdx.x;
    int w = tid >> 5, lane = tid & 31;
    int b = blockIdx.y;
    int i0 = blockIdx.x * 128;
    int g = lane >> 2, t4 = lane & 3;

    int laneRowB = (lane & 7) + ((lane & 16) >> 1);
    int laneKB   = (lane & 8) << 1;
    uint32_t loffB = (uint32_t)(laneRowB * WOROWB + laneKB);
    uint32_t smbase = (uint32_t)__cvta_generic_to_shared(csm);

    {
        int o = tid >> 2, qq = tid & 3;
        const float* src = wo + o * 64 + qq * 16;
        uint32_t hx[8];
#pragma unroll
        for (int u = 0; u < 8; u++) {
            float2 f2 = *(const float2*)(src + u * 2);
            hx[u] = packh2(f2.x, f2.y);
        }
        char* dst = csm + o * WOROWB + qq * 32;
        *(uint4*)dst = make_uint4(hx[0], hx[1], hx[2], hx[3]);
        *(uint4*)(dst + 16) = make_uint4(hx[4], hx[5], hx[6], hx[7]);
    }
    __syncthreads();

    int irow0 = i0 + w * 16 + g;
    int lbase = b * NNPOS + irow0;
    float l1a = __ldg(&g_pl[lbase]),     l2a = __ldg(&g_pl[BB * NNPOS + lbase]);
    float l1b = __ldg(&g_pl[lbase + 8]), l2b = __ldg(&g_pl[BB * NNPOS + lbase + 8]);
    float w1a = l1a / (l1a + l2a), w2a = l2a / (l1a + l2a);
    float w1b = l1b / (l1b + l2b), w2b = l2b / (l1b + l2b);

    const __half* p10 = g_po + (size_t)(b * NNPOS + irow0) * CC;
    const __half* p18 = p10 + 8 * CC;
    const __half* p20 = p10 + (size_t)(BB * NNPOS * CC);
    const __half* p28 = p20 + 8 * CC;

    uint32_t oA[4][4];
#pragma unroll
    for (int ks = 0; ks < 4; ks++) {
        int c0 = 16 * ks + 2 * t4;
        float2 aG  = __half22float2(*(const __half2*)(p10 + c0));
        float2 bG  = __half22float2(*(const __half2*)(p20 + c0));
        float2 aH  = __half22float2(*(const __half2*)(p18 + c0));
        float2 bH  = __half22float2(*(const __half2*)(p28 + c0));
        float2 aG2 = __half22float2(*(const __half2*)(p10 + c0 + 8));
        float2 bG2 = __half22float2(*(const __half2*)(p20 + c0 + 8));
        float2 aH2 = __half22float2(*(const __half2*)(p18 + c0 + 8));
        float2 bH2 = __half22float2(*(const __half2*)(p28 + c0 + 8));
        oA[ks][0] = packh2(aG.x * w1a + bG.x * w2a,   aG.y * w1a + bG.y * w2a);
        oA[ks][1] = packh2(aH.x * w1b + bH.x * w2b,   aH.y * w1b + bH.y * w2b);
        oA[ks][2] = packh2(aG2.x * w1a + bG2.x * w2a, aG2.y * w1a + bG2.y * w2a);
        oA[ks][3] = packh2(aH2.x * w1b + bH2.x * w2b, aH2.y * w1b + bH2.y * w2b);
    }

    float dacc[8][4] = {};
#pragma unroll
    for (int it = 0; it < 16; it++) {
        int ks = it >> 2, np = it & 3;
        uint32_t b4[4];
        ldsm4(b4, smbase + loffB + (uint32_t)(np * (16 * WOROWB) + ks * 32));
        mma16816(dacc[2 * np],     oA[ks], b4[0], b4[1]);
        mma16816(dacc[2 * np + 1], oA[ks], b4[2], b4[3]);
    }

#pragma unroll
    for (int nt = 0; nt < 8; nt++) {
        int o = nt * 8 + 2 * t4;
        float b0v = __ldg(&bo[o]), b1v = __ldg(&bo[o + 1]);
        size_t a00 = (size_t)(b * CC + o) * NNPOS + irow0;
        size_t a10 = a00 + NNPOS;
        out[a00]     = dacc[nt][0] + b0v + __ldg(&x[a00]);
        out[a10]     = dacc[nt][1] + b1v + __ldg(&x[a10]);
        out[a00 + 8] = dacc[nt][2] + b0v + __ldg(&x[a00 + 8]);
        out[a10 + 8] = dacc[nt][3] + b1v + __ldg(&x[a10 + 8]);
    }
}

// ---------------------------------------------------------------------------
extern "C" void kernel_launch(void* const* d_in, const int* in_sizes, int n_in,
                              void* d_out, int out_size) {
    (void)in_sizes; (void)n_in; (void)out_size;
    const float* x    = (const float*)d_in[0];
    const float* ln_g = (const float*)d_in[1];
    const float* ln_b = (const float*)d_in[2];
    const float* wq   = (const float*)d_in[3];
    const float* bq   = (const float*)d_in[4];
    const float* wk   = (const float*)d_in[5];
    const float* bk   = (const float*)d_in[6];
    const float* wv   = (const float*)d_in[7];
    const float* bv   = (const float*)d_in[8];
    const float* wo   = (const float*)d_in[9];
    const float* bo   = (const float*)d_in[10];
    float* out = (float*)d_out;

    cudaFuncSetAttribute(prep_kernel, cudaFuncAttributeMaxDynamicSharedMemorySize, PREP_SMEM);
    prep_kernel<<<dim3(32, BB), 256, PREP_SMEM>>>(x, ln_g, ln_b, wq, bq, wk, bk, wv, bv);
    cudaFuncSetAttribute(attn_kernel, cudaFuncAttributeMaxDynamicSharedMemorySize, ATTN_SMEM);
    attn_kernel<<<dim3(NNPOS / 128, BB, 2), 256, ATTN_SMEM>>>();
    combine_kernel<<<dim3(NNPOS / 128, BB), 256, COMB_SMEM>>>(wo, bo, x, out);
}

// round 17
// speedup vs baseline: 1.0102x; 1.0102x over previous
#include <cuda_runtime.h>
#include <cuda_fp16.h>
#include <cstdint>

#define BB 4
#define CC 64
#define NNPOS 4096
#define HH 64
#define WW 64

// Scratch (__device__ globals; no allocs allowed)
__device__ __half g_q[BB * NNPOS * CC];            // Q fp16 (B,N,C), x (0.125*log2e) folded
__device__ __half g_k[BB * CC * NNPOS];            // K fp16 (B,C,N)
__device__ __half g_v[BB * CC * NNPOS];            // V fp16 (B,C,N)
__device__ float  g_po[2 * BB * NNPOS * CC];       // partial O per key-half (B,N,C) fp32
__device__ float  g_pl[2 * BB * NNPOS];            // partial l per key-half

#define QSCALE 0.18033688011112293f   // 0.125 * log2(e)
#define ONES2 0x3C003C00u              // half2(1.0, 1.0)

// ---------------- helpers ----------------
__device__ __forceinline__ uint32_t h2u(__half2 h) { return *reinterpret_cast<uint32_t*>(&h); }
__device__ __forceinline__ uint32_t packh2(float a, float b) { return h2u(__floats2half2_rn(a, b)); }

__device__ __forceinline__ void ldsm4(uint32_t* r, uint32_t addr) {
    asm volatile("ldmatrix.sync.aligned.m8n8.x4.shared.b16 {%0,%1,%2,%3}, [%4];"
                 : "=r"(r[0]), "=r"(r[1]), "=r"(r[2]), "=r"(r[3]) : "r"(addr));
}
__device__ __forceinline__ void ldsm4t(uint32_t* r, uint32_t addr) {
    asm volatile("ldmatrix.sync.aligned.m8n8.x4.trans.shared.b16 {%0,%1,%2,%3}, [%4];"
                 : "=r"(r[0]), "=r"(r[1]), "=r"(r[2]), "=r"(r[3]) : "r"(addr));
}
__device__ __forceinline__ void mma16816(float* d, const uint32_t* a, uint32_t b0, uint32_t b1) {
    asm volatile("mma.sync.aligned.m16n8k16.row.col.f32.f16.f16.f32 "
                 "{%0,%1,%2,%3},{%4,%5,%6,%7},{%8,%9},{%0,%1,%2,%3};"
                 : "+f"(d[0]), "+f"(d[1]), "+f"(d[2]), "+f"(d[3])
                 : "r"(a[0]), "r"(a[1]), "r"(a[2]), "r"(a[3]), "r"(b0), "r"(b1));
}
__device__ __forceinline__ void mma16816h(uint32_t* d, const uint32_t* a, uint32_t b0, uint32_t b1) {
    asm volatile("mma.sync.aligned.m16n8k16.row.col.f16.f16.f16.f16 "
                 "{%0,%1},{%2,%3,%4,%5},{%6,%7},{%0,%1};"
                 : "+r"(d[0]), "+r"(d[1])
                 : "r"(a[0]), "r"(a[1]), "r"(a[2]), "r"(a[3]), "r"(b0), "r"(b1));
}
__device__ __forceinline__ void cpasync16(uint32_t dst, const void* src) {
    asm volatile("cp.async.cg.shared.global [%0], [%1], 16;" :: "r"(dst), "l"(src));
}
__device__ __forceinline__ void cpcommit() { asm volatile("cp.async.commit_group;"); }
__device__ __forceinline__ void cpwait0()  { asm volatile("cp.async.wait_group 0;"); }

__device__ __forceinline__ uint32_t ex2h2(uint32_t s) {
    uint32_t r;
    asm("ex2.approx.f16x2 %0, %1;" : "=r"(r) : "r"(s));
    return r;
}

// ---------------------------------------------------------------------------
// 1) Fused prep: LN + qproj (HMMA) + dwconv(k,v). grid (32, B), 256 threads.
// ---------------------------------------------------------------------------
#define PR_XSTR  264
#define WQROWB   144
#define PR_WQ    0
#define PR_WK    9216
#define PR_WV    11520
#define PR_BQ    13824
#define PR_BK    14080
#define PR_BV    14336
#define PR_XS    14592
#define PREP_SMEM (PR_XS + 64 * PR_XSTR * 2)   // 48384

__global__ __launch_bounds__(256) void prep_kernel(
    const float* __restrict__ x,
    const float* __restrict__ ln_g, const float* __restrict__ ln_b,
    const float* __restrict__ wq, const float* __restrict__ bq,
    const float* __restrict__ wk, const float* __restrict__ bk,
    const float* __restrict__ wv, const float* __restrict__ bv)
{
    extern __shared__ char psm[];
    float* Wk  = (float*)(psm + PR_WK);
    float* Wv  = (float*)(psm + PR_WV);
    float* Bq  = (float*)(psm + PR_BQ);
    float* Bk  = (float*)(psm + PR_BK);
    float* Bv  = (float*)(psm + PR_BV);
    __half* Xs = (__half*)(psm + PR_XS);

    int tid = threadIdx.x;
    int h0 = blockIdx.x * 2;
    int b = blockIdx.y;

    // stage wq -> smem fp16 [o][c], stride WQROWB
    {
        int o = tid >> 2, qq = tid & 3;
        const float* src = wq + o * 64 + qq * 16;
        uint32_t hx[8];
#pragma unroll
        for (int u = 0; u < 8; u++) {
            float2 f2 = *(const float2*)(src + u * 2);
            hx[u] = packh2(f2.x, f2.y);
        }
        char* dst = psm + PR_WQ + o * WQROWB + qq * 32;
        *(uint4*)dst = make_uint4(hx[0], hx[1], hx[2], hx[3]);
        *(uint4*)(dst + 16) = make_uint4(hx[4], hx[5], hx[6], hx[7]);
    }
    for (int t = tid; t < 576; t += 256) { Wk[t] = wk[t]; Wv[t] = wv[t]; }
    if (tid < 64) { Bq[tid] = bq[tid]; Bk[tid] = bk[tid]; Bv[tid] = bv[tid]; }

    // Phase 1: LN rows h0-1 .. h0+2 (zero pad) -> Xs[c][tid]
    {
        int hh = tid >> 6;
        int w  = tid & 63;
        int h = h0 - 1 + hh;
        if (h >= 0 && h < HH) {
            const float* xp = x + (size_t)b * CC * NNPOS + h * WW + w;
            float vals[CC];
            float s = 0.f;
#pragma unroll
            for (int c = 0; c < CC; c++) { vals[c] = xp[(size_t)c * NNPOS]; s += vals[c]; }
            float mu = s * (1.f / 64.f);
            float vs = 0.f;
#pragma unroll
            for (int c = 0; c < CC; c++) { float d = vals[c] - mu; vs += d * d; }
            float rstd = rsqrtf(vs * (1.f / 64.f) + 1e-5f);
#pragma unroll
            for (int c = 0; c < CC; c++)
                Xs[c * PR_XSTR + tid] = __float2half_rn((vals[c] - mu) * rstd * __ldg(&ln_g[c]) + __ldg(&ln_b[c]));
        } else {
#pragma unroll
            for (int c = 0; c < CC; c++) Xs[c * PR_XSTR + tid] = __ushort_as_half((unsigned short)0);
        }
    }
    __syncthreads();

    // Phase 2: qproj via HMMA. warp w -> 16 positions.
    {
        int w = tid >> 5, lane = tid & 31;
        int g = lane >> 2, t4 = lane & 3;
        uint32_t xsbase = (uint32_t)__cvta_generic_to_shared(psm + PR_XS);
        uint32_t wqbase = (uint32_t)__cvta_generic_to_shared(psm + PR_WQ);

        int cA = (lane & 7) + ((lane & 16) >> 1);
        int posCh = ((lane >> 3) & 1) * 8;
        uint32_t aaddr = xsbase + (uint32_t)((cA * PR_XSTR + 64 + w * 16 + posCh) * 2);
        uint32_t qAf[4][4];
#pragma unroll
        for (int ks = 0; ks < 4; ks++)
            ldsm4t(qAf[ks], aaddr + (uint32_t)(ks * 16 * PR_XSTR * 2));

        int laneRowB = (lane & 7) + ((lane & 16) >> 1);
        int laneKB   = (lane & 8) << 1;
        uint32_t wqb = wqbase + (uint32_t)(laneRowB * WQROWB + laneKB);

        float dacc[8][4] = {};
#pragma unroll
        for (int it = 0; it < 16; it++) {
            int ks = it >> 2, np = it & 3;
            uint32_t b4[4];
            ldsm4(b4, wqb + (uint32_t)(np * (16 * WQROWB) + ks * 32));
            mma16816(dacc[2 * np],     qAf[ks], b4[0], b4[1]);
            mma16816(dacc[2 * np + 1], qAf[ks], b4[2], b4[3]);
        }

        int p0 = h0 * WW + w * 16 + g;
        __half* qr0 = g_q + (size_t)(b * NNPOS + p0) * CC;
        __half* qr8 = qr0 + 8 * CC;
#pragma unroll
        for (int nt = 0; nt < 8; nt++) {
            int o = nt * 8 + 2 * t4;
            float b0v = Bq[o], b1v = Bq[o + 1];
            *(uint32_t*)(qr0 + o) = packh2((dacc[nt][0] + b0v) * QSCALE,
                                           (dacc[nt][1] + b1v) * QSCALE);
            *(uint32_t*)(qr8 + o) = packh2((dacc[nt][2] + b0v) * QSCALE,
                                           (dacc[nt][3] + b1v) * QSCALE);
        }
    }

    // Phase 3: dwconv.
    {
        int c = tid >> 2, row = (tid >> 1) & 1, wh = tid & 1;
        int wst = wh * 32;
        float wkr[9], wvr[9];
#pragma unroll
        for (int i = 0; i < 9; i++) { wkr[i] = Wk[c * 9 + i]; wvr[i] = Wv[c * 9 + i]; }
        float bk0 = Bk[c], bv0 = Bv[c];
        uint32_t kh[16], vh[16];
#pragma unroll
        for (int ch = 0; ch < 4; ch++) {
            int w0 = wst + ch * 8;
            float ff[3][10];
#pragma unroll
            for (int r = 0; r < 3; r++) {
                const __half* src = Xs + c * PR_XSTR + (row + r) * 64 + (w0 - 2);
                float2 t0 = __half22float2(*(const __half2*)(src));
                float2 t1 = __half22float2(*(const __half2*)(src + 2));
                float2 t2 = __half22float2(*(const __half2*)(src + 4));
                float2 t3 = __half22float2(*(const __half2*)(src + 6));
                float2 t4v = __half22float2(*(const __half2*)(src + 8));
                float2 t5 = __half22float2(*(const __half2*)(src + 10));
                ff[r][0] = t0.y; ff[r][1] = t1.x; ff[r][2] = t1.y; ff[r][3] = t2.x; ff[r][4] = t2.y;
                ff[r][5] = t3.x; ff[r][6] = t3.y; ff[r][7] = t4v.x; ff[r][8] = t4v.y; ff[r][9] = t5.x;
            }
            if (w0 == 0)  { ff[0][0] = 0.f; ff[1][0] = 0.f; ff[2][0] = 0.f; }
            if (w0 == 56) { ff[0][9] = 0.f; ff[1][9] = 0.f; ff[2][9] = 0.f; }
            float ko[8], vo[8];
#pragma unroll
            for (int o = 0; o < 8; o++) {
                float sk = bk0, sv = bv0;
#pragma unroll
                for (int r = 0; r < 3; r++)
#pragma unroll
                    for (int d = 0; d < 3; d++) {
                        float xv = ff[r][o + d];
                        sk += xv * wkr[r * 3 + d];
                        sv += xv * wvr[r * 3 + d];
                    }
                ko[o] = sk; vo[o] = sv;
            }
#pragma unroll
            for (int j = 0; j < 4; j++) {
                kh[ch * 4 + j] = packh2(ko[2 * j], ko[2 * j + 1]);
                vh[ch * 4 + j] = packh2(vo[2 * j], vo[2 * j + 1]);
            }
        }
        size_t base = (size_t)(b * CC + c) * NNPOS + (h0 + row) * WW + wst;
        __half* kd = g_k + base;
        __half* vd = g_v + base;
        *(uint4*)(kd)      = make_uint4(kh[0],  kh[1],  kh[2],  kh[3]);
        *(uint4*)(kd + 8)  = make_uint4(kh[4],  kh[5],  kh[6],  kh[7]);
        *(uint4*)(kd + 16) = make_uint4(kh[8],  kh[9],  kh[10], kh[11]);
        *(uint4*)(kd + 24) = make_uint4(kh[12], kh[13], kh[14], kh[15]);
        *(uint4*)(vd)      = make_uint4(vh[0],  vh[1],  vh[2],  vh[3]);
        *(uint4*)(vd + 8)  = make_uint4(vh[4],  vh[5],  vh[6],  vh[7]);
        *(uint4*)(vd + 16) = make_uint4(vh[8],  vh[9],  vh[10], vh[11]);
        *(uint4*)(vd + 24) = make_uint4(vh[12], vh[13], vh[14], vh[15]);
    }
}

// ---------------------------------------------------------------------------
// 2) HMMA flash attention, split-KV, distance-2 ldsm pipelining.
//    grid (32, B, 2), 256 threads, 2 CTAs/SM.
// ---------------------------------------------------------------------------
#define TROWB 272
#define TBYTES (64 * TROWB)         // 17408
#define BUFB (2 * TBYTES)           // 34816
#define ATTN_SMEM (2 * BUFB)        // 69632

__device__ __forceinline__ void prefetch_tile(char* smp, int s, int b, int jt, int tid) {
    int c = tid >> 2, q = tid & 3;
    size_t src_off = (size_t)(b * CC + c) * NNPOS + jt + q * 32;
    uint32_t dst = (uint32_t)__cvta_generic_to_shared(smp + s * BUFB + c * TROWB + q * 64);
    const __half* ks = g_k + src_off;
    const __half* vs = g_v + src_off;
#pragma unroll
    for (int u = 0; u < 4; u++) cpasync16(dst + u * 16, ks + u * 8);
#pragma unroll
    for (int u = 0; u < 4; u++) cpasync16(dst + TBYTES + u * 16, vs + u * 8);
}

__global__ __launch_bounds__(256, 2) void attn_kernel() {
    extern __shared__ char smp[];
    int tid = threadIdx.x;
    int w = tid >> 5, lane = tid & 31;
    int b = blockIdx.y;
    int i0 = blockIdx.x * 128;
    int half = blockIdx.z;
    int jt0 = half * 2048;
    int g = lane >> 2, t4 = lane & 3;

    uint32_t loffK = (uint32_t)((lane & 15) * TROWB + ((lane >> 4) << 4));
    int laneRowB = (lane & 7) + ((lane & 16) >> 1);
    int laneKB   = (lane & 8) << 1;
    uint32_t loffV = (uint32_t)(laneRowB * TROWB + laneKB);
    uint32_t smbase = (uint32_t)__cvta_generic_to_shared(smp);

    prefetch_tile(smp, 0, b, jt0, tid);
    cpcommit();

    uint32_t qA[4][4];
    {
        size_t row0 = (size_t)(b * NNPOS + i0 + w * 16 + g) * CC;
        size_t row8 = row0 + 8 * CC;
#pragma unroll
        for (int ks = 0; ks < 4; ks++) {
            int col = 2 * t4 + 16 * ks;
            qA[ks][0] = *(const uint32_t*)(g_q + row0 + col);
            qA[ks][1] = *(const uint32_t*)(g_q + row8 + col);
            qA[ks][2] = *(const uint32_t*)(g_q + row0 + col + 8);
            qA[ks][3] = *(const uint32_t*)(g_q + row8 + col + 8);
        }
    }

    float oacc[8][4] = {};
    float lacc[4] = {};

    for (int tix = 0; tix < 16; tix++) {
        cpwait0();
        __syncthreads();
        if (tix < 15) { prefetch_tile(smp, (tix + 1) & 1, b, jt0 + (tix + 1) * 128, tid); cpcommit(); }

        uint32_t kb = smbase + (uint32_t)((tix & 1) * BUFB) + loffK;
        uint32_t vb = smbase + (uint32_t)((tix & 1) * BUFB + TBYTES) + loffV;

        // S = Q K^T (fp16 accumulate), trans-ldsm, distance-2 pipeline
        uint32_t sacc16[16][2];
#pragma unroll
        for (int i = 0; i < 16; i++) { sacc16[i][0] = 0u; sacc16[i][1] = 0u; }
        {
            uint32_t b4[3][4];
            ldsm4t(b4[0], kb);
            ldsm4t(b4[1], kb + 32u);
#pragma unroll
            for (int it = 0; it < 32; it++) {
                int ks = it >> 3, np = it & 7;
                int cur = it % 3;
                if (it < 30) {
                    int nx = it + 2;
                    ldsm4t(b4[nx % 3], kb + (uint32_t)((nx & 7) * 32 + (nx >> 3) * (16 * TROWB)));
                }
                mma16816h(sacc16[2 * np],     qA[ks], b4[cur][0], b4[cur][1]);
                mma16816h(sacc16[2 * np + 1], qA[ks], b4[cur][2], b4[cur][3]);
            }
        }

        // p = 2^S; l via ones-MMA; O += P V^T; distance-2 ldsm pipeline
        {
            uint32_t v4[3][4];
            ldsm4(v4[0], vb);
            ldsm4(v4[1], vb + (uint32_t)(16 * TROWB));
#pragma unroll
            for (int ks2 = 0; ks2 < 8; ks2++) {
                uint32_t pA[4];
                pA[0] = ex2h2(sacc16[2 * ks2][0]);
                pA[1] = ex2h2(sacc16[2 * ks2][1]);
                pA[2] = ex2h2(sacc16[2 * ks2 + 1][0]);
                pA[3] = ex2h2(sacc16[2 * ks2 + 1][1]);
                mma16816(lacc, pA, ONES2, ONES2);
#pragma unroll
                for (int np = 0; np < 4; np++) {
                    int it = ks2 * 4 + np;
                    int cur = it % 3;
                    if (it < 30) {
                        int nx = it + 2;
                        ldsm4(v4[nx % 3], vb + (uint32_t)((nx & 3) * (16 * TROWB) + (nx >> 2) * 32));
                    }
                    mma16816(oacc[2 * np],     pA, v4[cur][0], v4[cur][1]);
                    mma16816(oacc[2 * np + 1], pA, v4[cur][2], v4[cur][3]);
                }
            }
        }
    }

    // write partial O (B,N,C fp32) + partial l
    int irow0 = i0 + w * 16 + g;
    float* po0 = g_po + (size_t)half * (BB * NNPOS * CC) + (size_t)(b * NNPOS + irow0) * CC;
    float* po8 = po0 + 8 * CC;
#pragma unroll
    for (int nt = 0; nt < 8; nt++) {
        int c = nt * 8 + 2 * t4;
        *(float2*)&po0[c] = make_float2(oacc[nt][0], oacc[nt][1]);
        *(float2*)&po8[c] = make_float2(oacc[nt][2], oacc[nt][3]);
    }
    if (t4 == 0) {
        g_pl[half * (BB * NNPOS) + b * NNPOS + irow0]     = lacc[0];
        g_pl[half * (BB * NNPOS) + b * NNPOS + irow0 + 8] = lacc[2];
    }
}

// ---------------------------------------------------------------------------
// 3) Combine: O = (O1+O2)/(l1+l2), out = O @ wo^T + bo + x.
// ---------------------------------------------------------------------------
#define WOROWB 144
#define COMB_SMEM (64 * WOROWB)

__global__ __launch_bounds__(256) void combine_kernel(const float* __restrict__ wo,
                                                      const float* __restrict__ bo,
                                                      const float* __restrict__ x,
                                                      float* __restrict__ out) {
    extern __shared__ char csm[];
    int tid = threadIdx.x;
    int w = tid >> 5, lane = tid & 31;
    int b = blockIdx.y;
    int i0 = blockIdx.x * 128;
    int g = lane >> 2, t4 = lane & 3;

    int laneRowB = (lane & 7) + ((lane & 16) >> 1);
    int laneKB   = (lane & 8) << 1;
    uint32_t loffB = (uint32_t)(laneRowB * WOROWB + laneKB);
    uint32_t smbase = (uint32_t)__cvta_generic_to_shared(csm);

    {
        int o = tid >> 2, qq = tid & 3;
        const float* src = wo + o * 64 + qq * 16;
        uint32_t hx[8];
#pragma unroll
        for (int u = 0; u < 8; u++) {
            float2 f2 = *(const float2*)(src + u * 2);
            hx[u] = packh2(f2.x, f2.y);
        }
        char* dst = csm + o * WOROWB + qq * 32;
        *(uint4*)dst = make_uint4(hx[0], hx[1], hx[2], hx[3]);
        *(uint4*)(dst + 16) = make_uint4(hx[4], hx[5], hx[6], hx[7]);
    }
    __syncthreads();

    int irow0 = i0 + w * 16 + g;
    int lbase = b * NNPOS + irow0;
    float inv0 = 1.f / (__ldg(&g_pl[lbase]) + __ldg(&g_pl[BB * NNPOS + lbase]));
    float inv1 = 1.f / (__ldg(&g_pl[lbase + 8]) + __ldg(&g_pl[BB * NNPOS + lbase + 8]));

    const float* p10 = g_po + (size_t)(b * NNPOS + irow0) * CC;
    const float* p18 = p10 + 8 * CC;
    const float* p20 = p10 + (size_t)(BB * NNPOS * CC);
    const float* p28 = p20 + 8 * CC;

    uint32_t oA[4][4];
#pragma unroll
    for (int ks = 0; ks < 4; ks++) {
        int c0 = 16 * ks + 2 * t4;
        float2 aG  = *(const float2*)&p10[c0];
        float2 bG  = *(const float2*)&p20[c0];
        float2 aH  = *(const float2*)&p18[c0];
        float2 bH  = *(const float2*)&p28[c0];
        float2 aG2 = *(const float2*)&p10[c0 + 8];
        float2 bG2 = *(const float2*)&p20[c0 + 8];
        float2 aH2 = *(const float2*)&p18[c0 + 8];
        float2 bH2 = *(const float2*)&p28[c0 + 8];
        oA[ks][0] = packh2((aG.x + bG.x) * inv0,   (aG.y + bG.y) * inv0);
        oA[ks][1] = packh2((aH.x + bH.x) * inv1,   (aH.y + bH.y) * inv1);
        oA[ks][2] = packh2((aG2.x + bG2.x) * inv0, (aG2.y + bG2.y) * inv0);
        oA[ks][3] = packh2((aH2.x + bH2.x) * inv1, (aH2.y + bH2.y) * inv1);
    }

    float dacc[8][4] = {};
#pragma unroll
    for (int it = 0; it < 16; it++) {
        int ks = it >> 2, np = it & 3;
        uint32_t b4[4];
        ldsm4(b4, smbase + loffB + (uint32_t)(np * (16 * WOROWB) + ks * 32));
        mma16816(dacc[2 * np],     oA[ks], b4[0], b4[1]);
        mma16816(dacc[2 * np + 1], oA[ks], b4[2], b4[3]);
    }

#pragma unroll
    for (int nt = 0; nt < 8; nt++) {
        int o = nt * 8 + 2 * t4;
        float b0v = __ldg(&bo[o]), b1v = __ldg(&bo[o + 1]);
        size_t a00 = (size_t)(b * CC + o) * NNPOS + irow0;
        size_t a10 = a00 + NNPOS;
        out[a00]     = dacc[nt][0] + b0v + __ldg(&x[a00]);
        out[a10]     = dacc[nt][1] + b1v + __ldg(&x[a10]);
        out[a00 + 8] = dacc[nt][2] + b0v + __ldg(&x[a00 + 8]);
        out[a10 + 8] = dacc[nt][3] + b1v + __ldg(&x[a10 + 8]);
    }
}

// ---------------------------------------------------------------------------
extern "C" void kernel_launch(void* const* d_in, const int* in_sizes, int n_in,
                              void* d_out, int out_size) {
    (void)in_sizes; (void)n_in; (void)out_size;
    const float* x    = (const float*)d_in[0];
    const float* ln_g = (const float*)d_in[1];
    const float* ln_b = (const float*)d_in[2];
    const float* wq   = (const float*)d_in[3];
    const float* bq   = (const float*)d_in[4];
    const float* wk   = (const float*)d_in[5];
    const float* bk   = (const float*)d_in[6];
    const float* wv   = (const float*)d_in[7];
    const float* bv   = (const float*)d_in[8];
    const float* wo   = (const float*)d_in[9];
    const float* bo   = (const float*)d_in[10];
    float* out = (float*)d_out;

    cudaFuncSetAttribute(prep_kernel, cudaFuncAttributeMaxDynamicSharedMemorySize, PREP_SMEM);
    prep_kernel<<<dim3(32, BB), 256, PREP_SMEM>>>(x, ln_g, ln_b, wq, bq, wk, bk, wv, bv);
    cudaFuncSetAttribute(attn_kernel, cudaFuncAttributeMaxDynamicSharedMemorySize, ATTN_SMEM);
    attn_kernel<<<dim3(NNPOS / 128, BB, 2), 256, ATTN_SMEM>>>();
    combine_kernel<<<dim3(NNPOS / 128, BB), 256, COMB_SMEM>>>(wo, bo, x, out);
}